// round 1
// baseline (speedup 1.0000x reference)
#include <cuda_runtime.h>
#include <math.h>

// Problem dims
#define TT   8192
#define DIN  2048
#define DD   512
#define HH   512
#define AA   18
#define H3   (3*HH)       // 1536
#define GCTAS 64          // CTAs in the persistent GRU kernel (<=148, co-resident)

// Output layout (flattened concat of (policy, value, hT))
#define P_OFF  0
#define V_OFF  (TT*AA)            // 147456
#define HT_OFF (TT*AA + TT)       // 155648

// ---------------- device scratch (no allocations allowed) ----------------
__device__ float g_z1[TT*DD];
__device__ float g_z2[TT*DD];
__device__ float g_X [TT*H3];
__device__ float g_seq[TT*HH];
__device__ float g_h[2][HH];
__device__ int   g_counter;

__device__ __forceinline__ float sigmoidf_(float x) {
    return 1.0f / (1.0f + __expf(-x));
}

// ---------------- fp32 SGEMM: C = act(A[MxK] @ B[KxN] + bias[N]) ----------------
// 128x128 tile, BK=8, 256 threads, 8x8 micro-tile per thread.
template<bool RELU>
__global__ __launch_bounds__(256)
void sgemm_bias(const float* __restrict__ A, const float* __restrict__ B,
                const float* __restrict__ bias, float* __restrict__ C,
                int M, int N, int K)
{
    __shared__ float As[8][128];
    __shared__ float Bs[8][128];

    const int tid = threadIdx.x;
    const int bm = blockIdx.y * 128;
    const int bn = blockIdx.x * 128;

    // A tile loader: 128 rows x 8 cols, each thread one float4
    const int arow = tid >> 1;              // 0..127
    const int acol = (tid & 1) << 2;        // 0 or 4
    // B tile loader: 8 rows x 128 cols
    const int brow = tid >> 5;              // 0..7
    const int bcol = (tid & 31) << 2;       // 0..124

    const int ty = tid >> 4, tx = tid & 15;
    const int row0 = ty << 3;               // 0..120
    const int col0 = tx << 3;               // 0..120

    float c[8][8];
    #pragma unroll
    for (int i = 0; i < 8; i++)
        #pragma unroll
        for (int j = 0; j < 8; j++) c[i][j] = 0.0f;

    for (int k0 = 0; k0 < K; k0 += 8) {
        float4 a4 = *(const float4*)&A[(size_t)(bm + arow) * K + k0 + acol];
        As[acol + 0][arow] = a4.x;
        As[acol + 1][arow] = a4.y;
        As[acol + 2][arow] = a4.z;
        As[acol + 3][arow] = a4.w;
        *(float4*)&Bs[brow][bcol] =
            *(const float4*)&B[(size_t)(k0 + brow) * N + bn + bcol];
        __syncthreads();

        #pragma unroll
        for (int kk = 0; kk < 8; kk++) {
            float4 a0 = *(const float4*)&As[kk][row0];
            float4 a1 = *(const float4*)&As[kk][row0 + 4];
            float4 b0 = *(const float4*)&Bs[kk][col0];
            float4 b1 = *(const float4*)&Bs[kk][col0 + 4];
            float ar[8] = {a0.x,a0.y,a0.z,a0.w,a1.x,a1.y,a1.z,a1.w};
            float br[8] = {b0.x,b0.y,b0.z,b0.w,b1.x,b1.y,b1.z,b1.w};
            #pragma unroll
            for (int i = 0; i < 8; i++)
                #pragma unroll
                for (int j = 0; j < 8; j++)
                    c[i][j] = fmaf(ar[i], br[j], c[i][j]);
        }
        __syncthreads();
    }

    #pragma unroll
    for (int i = 0; i < 8; i++) {
        #pragma unroll
        for (int j = 0; j < 8; j++) {
            float v = c[i][j] + bias[bn + col0 + j];
            if (RELU) v = fmaxf(v, 0.0f);
            C[(size_t)(bm + row0 + i) * N + bn + col0 + j] = v;
        }
    }
}

// ---------------- init: h0 <- prev_hidden, counter <- 0 ----------------
__global__ void init_kernel(const float* __restrict__ prev_hidden)
{
    int i = threadIdx.x;
    if (i < HH) g_h[0][i] = prev_hidden[i];
    if (i == 0) g_counter = 0;
}

// ---------------- persistent GRU scan ----------------
// 64 CTAs x 192 threads. CTA `blk` owns h-indices [blk*8, blk*8+8).
// It computes rec columns {g*512 + blk*8 + j : g in 0..2, j in 0..7} (24 cols).
// Thread layout: tid = s*24 + c, s in 0..7 (K segment), c in 0..23 (column).
// Each thread caches its 64 Ug weights in registers.
__global__ __launch_bounds__(192, 1)
void gru_kernel(const float* __restrict__ Ug, const float* __restrict__ bg,
                float* __restrict__ out)
{
    __shared__ float sh_h[HH];
    __shared__ float sh_part[192];
    __shared__ float sh_x[24];
    __shared__ float sh_rec[24];

    const int tid = threadIdx.x;
    const int blk = blockIdx.x;
    const int s = tid / 24;          // 0..7
    const int c = tid % 24;          // 0..23
    const int gate = c >> 3;         // 0..2
    const int j = c & 7;             // 0..7
    const int col = gate * HH + blk * 8 + j;   // global column in [0,1536)

    // Cache weight slice in registers: w[i] = Ug[s*64+i][col]
    float w[64];
    #pragma unroll
    for (int i = 0; i < 64; i++)
        w[i] = Ug[(size_t)(s * 64 + i) * H3 + col];

    const float brec = (tid < 24) ? bg[H3 + col] : 0.0f;   // bg[1] row

    for (int t = 0; t < TT; t++) {
        // Prefetch this step's X values (independent of h) — hides load latency
        float xv = 0.0f;
        if (tid < 24) xv = g_X[(size_t)t * H3 + col];   // tid<24 => s==0, col valid

        // Wait for all CTAs to finish step t-1
        if (tid == 0 && t > 0) {
            const int target = GCTAS * t;
            while (*((volatile int*)&g_counter) < target) { }
            __threadfence();
        }
        __syncthreads();

        const int par = t & 1;
        for (int i = tid; i < HH; i += 192) sh_h[i] = g_h[par][i];
        if (tid < 24) sh_x[tid] = xv;
        __syncthreads();

        // 512-long dot for this thread's 64-element segment (4 accum chains)
        const float4* hp = (const float4*)&sh_h[s * 64];
        float a0 = 0.f, a1 = 0.f, a2 = 0.f, a3 = 0.f;
        #pragma unroll
        for (int i = 0; i < 16; i++) {
            float4 h4 = hp[i];
            a0 = fmaf(w[4*i+0], h4.x, a0);
            a1 = fmaf(w[4*i+1], h4.y, a1);
            a2 = fmaf(w[4*i+2], h4.z, a2);
            a3 = fmaf(w[4*i+3], h4.w, a3);
        }
        sh_part[tid] = (a0 + a1) + (a2 + a3);
        __syncthreads();

        if (tid < 24) {
            float r = brec;
            #pragma unroll
            for (int ss = 0; ss < 8; ss++) r += sh_part[ss * 24 + tid];
            sh_rec[tid] = r;
        }
        __syncthreads();

        if (tid < 8) {
            const float rz = sh_rec[tid], rr = sh_rec[8 + tid], rh = sh_rec[16 + tid];
            const float xz = sh_x[tid],   xr = sh_x[8 + tid],   xh = sh_x[16 + tid];
            const float zt = sigmoidf_(xz + rz);
            const float rt = sigmoidf_(xr + rr);
            const float hh = sigmoidf_(xh + rt * rh);
            const float hprev = sh_h[blk * 8 + tid];
            const float hn = zt * hprev + (1.0f - zt) * hh;
            g_h[par ^ 1][blk * 8 + tid] = hn;
            g_seq[(size_t)t * HH + blk * 8 + tid] = hn;
            __threadfence();
        }
        __syncthreads();
        if (tid == 0) {
            __threadfence();
            atomicAdd(&g_counter, 1);
        }
    }

    // hT = final hidden state (this CTA's own slice — own writes are visible)
    if (tid < 8) out[HT_OFF + blk * 8 + tid] = g_seq[(size_t)(TT - 1) * HH + blk * 8 + tid];
}

// ---------------- policy softmax + value head ----------------
// One warp per timestep; lanes 0..17 -> policy logits, lane 18 -> value.
__global__ __launch_bounds__(256)
void policy_value_kernel(const float* __restrict__ Wp, const float* __restrict__ bp,
                         const float* __restrict__ Wv, const float* __restrict__ bv,
                         float* __restrict__ out)
{
    __shared__ float srow[8][HH];
    const int warp = threadIdx.x >> 5;
    const int lane = threadIdx.x & 31;
    const int t = blockIdx.x * 8 + warp;

    // stage seq row into smem
    const float4* rp = (const float4*)&g_seq[(size_t)t * HH];
    float4* sp = (float4*)&srow[warp][0];
    for (int i = lane; i < HH / 4; i += 32) sp[i] = rp[i];
    __syncwarp();

    // uniform loop over k; lane-dependent weight column
    const float* wcol; int stride; float acc;
    if (lane < AA)       { wcol = Wp + lane; stride = AA; acc = bp[lane]; }
    else if (lane == AA) { wcol = Wv;        stride = 1;  acc = bv[0];    }
    else                 { wcol = Wv;        stride = 0;  acc = 0.0f;     }

    #pragma unroll 4
    for (int k = 0; k < HH; k++)
        acc = fmaf(srow[warp][k], wcol[(size_t)k * stride], acc);

    // softmax over lanes 0..17
    float lv = (lane < AA) ? acc : -INFINITY;
    float m = lv;
    #pragma unroll
    for (int o = 16; o; o >>= 1) m = fmaxf(m, __shfl_xor_sync(0xffffffffu, m, o));
    float e = (lane < AA) ? __expf(acc - m) : 0.0f;
    float sum = e;
    #pragma unroll
    for (int o = 16; o; o >>= 1) sum += __shfl_xor_sync(0xffffffffu, sum, o);

    if (lane < AA)  out[P_OFF + (size_t)t * AA + lane] = e / sum;
    if (lane == AA) out[V_OFF + t] = acc;
}

// ---------------- launch ----------------
extern "C" void kernel_launch(void* const* d_in, const int* in_sizes, int n_in,
                              void* d_out, int out_size)
{
    (void)in_sizes; (void)n_in; (void)out_size;
    const float* x    = (const float*)d_in[0];
    const float* ph   = (const float*)d_in[1];
    const float* W1   = (const float*)d_in[2];
    const float* b1   = (const float*)d_in[3];
    const float* W2   = (const float*)d_in[4];
    const float* b2   = (const float*)d_in[5];
    const float* Wg   = (const float*)d_in[6];
    const float* Ug   = (const float*)d_in[7];
    const float* bg   = (const float*)d_in[8];
    const float* Wp   = (const float*)d_in[9];
    const float* bp   = (const float*)d_in[10];
    const float* Wv   = (const float*)d_in[11];
    const float* bv   = (const float*)d_in[12];
    float* out = (float*)d_out;

    float *z1, *z2, *X;
    cudaGetSymbolAddress((void**)&z1, g_z1);
    cudaGetSymbolAddress((void**)&z2, g_z2);
    cudaGetSymbolAddress((void**)&X,  g_X);

    // z1 = relu(x @ W1 + b1)
    sgemm_bias<true ><<<dim3(DD/128, TT/128), 256>>>(x,  W1, b1, z1, TT, DD, DIN);
    // z2 = relu(z1 @ W2 + b2)
    sgemm_bias<true ><<<dim3(DD/128, TT/128), 256>>>(z1, W2, b2, z2, TT, DD, DD);
    // X = z2 @ Wg + bg[0]
    sgemm_bias<false><<<dim3(H3/128, TT/128), 256>>>(z2, Wg, bg, X,  TT, H3, DD);

    init_kernel<<<1, 512>>>(ph);
    gru_kernel<<<GCTAS, 192>>>(Ug, bg, out);
    policy_value_kernel<<<TT/8, 256>>>(Wp, bp, Wv, bv, out);
}